// round 1
// baseline (speedup 1.0000x reference)
#include <cuda_runtime.h>
#include <cuda_bf16.h>
#include <math.h>

#define BB   4096
#define FF   24
#define VV   1000
#define DD   32
#define FD   768          // F*D
#define COMB 1536         // 2*F*D
#define H0N  1024
#define H1N  512
#define RED  8
#define EPSV 1e-5f

// ---------------- device scratch (no allocations allowed) ----------------
__device__ __align__(16) float g_E2[2 * BB * FD];     // rows 0..B-1: e, rows B..2B-1: A*e
__device__ __align__(16) float g_WT[FD * FD];         // WT[(j*D+l)*768 + (i*D+k)] = W[i,j,k,l]
__device__ __align__(16) float g_S[2 * BB * FD];      // full-contraction results (p-sum, q-sum)
__device__ __align__(16) float g_comb[BB * COMB];
__device__ __align__(16) float g_h0[BB * H0N];
__device__ __align__(16) float g_h1[BB * H1N];
__device__ float g_A[BB * FF];
__device__ float g_lin[BB];
__device__ float g_scale0[H0N], g_shift0[H0N];
__device__ float g_scale1[H1N], g_shift1[H1N];

// ---------------- K0: rearrange bilinear W into GEMM-B layout -------------
__global__ void transposeW_kernel(const float* __restrict__ W, float* __restrict__ WT) {
    int o = blockIdx.x * 256 + threadIdx.x;      // o in [0, 768*768)
    int ik = o % FD, jl = o / FD;
    int i = ik >> 5, k = ik & 31, j = jl >> 5, l = jl & 31;
    WT[o] = W[(((i * FF + j) * DD + k) * DD) + l];
}

// ---------------- K1: gather + linear + SENet -----------------------------
__global__ void gather_se_kernel(const int* __restrict__ x,
                                 const float* __restrict__ emb,
                                 const float* __restrict__ lint,
                                 const float* __restrict__ sw1,
                                 const float* __restrict__ sw2,
                                 float* __restrict__ E2,
                                 float* __restrict__ Apar,
                                 float* __restrict__ linout) {
    int b = blockIdx.x;
    int t = threadIdx.x;
    __shared__ int   xs[FF];
    __shared__ float es[FD];
    __shared__ float Zs[FF], hid[RED], As[FF], linp[FF];

    if (t < FF) xs[t] = x[b * FF + t];
    __syncthreads();

    #pragma unroll
    for (int r = 0; r < 3; r++) {
        int ik = t + r * 256;
        int f = ik >> 5, d = ik & 31;
        es[ik] = emb[((long)f * VV + xs[f]) * DD + d];
    }
    if (t < FF) linp[t] = lint[(long)t * VV + xs[t]];
    __syncthreads();

    // squeeze: mean over D per field (warp w -> fields 3w..3w+2)
    int w = t >> 5, lane = t & 31;
    #pragma unroll
    for (int ff = 0; ff < 3; ff++) {
        int f = w * 3 + ff;
        float v = es[f * 32 + lane];
        #pragma unroll
        for (int o = 16; o > 0; o >>= 1) v += __shfl_xor_sync(0xffffffffu, v, o);
        if (lane == 0) Zs[f] = v * (1.f / 32.f);
    }
    __syncthreads();
    if (t < RED) {
        float s = 0.f;
        #pragma unroll
        for (int f = 0; f < FF; f++) s += Zs[f] * sw1[t * FF + f];
        hid[t] = fmaxf(s, 0.f);
    }
    __syncthreads();
    if (t < FF) {
        float s = 0.f;
        #pragma unroll
        for (int r = 0; r < RED; r++) s += hid[r] * sw2[t * RED + r];
        As[t] = 1.f / (1.f + expf(-s));
    }
    if (t == 0) {
        float s = 0.f;
        #pragma unroll
        for (int f = 0; f < FF; f++) s += linp[f];
        linout[b] = s;
    }
    __syncthreads();

    #pragma unroll
    for (int r = 0; r < 3; r++) {
        int ik = t + r * 256;
        int f = ik >> 5;
        float e = es[ik];
        E2[(long)b * FD + ik] = e;
        E2[(long)(BB + b) * FD + ik] = As[f] * e;
    }
    if (t < FF) Apar[b * FF + t] = As[t];
}

// ---------------- generic 128x128x16 SGEMM --------------------------------
// C[M,N] = op(A[M,K]) @ B[K,N] (+ bias[n]).  op = identity or BN+ReLU on A cols.
// M,N multiples of 128; K multiple of 16. Row-major everything.
template <bool TRANSA, bool BIAS>
__global__ void __launch_bounds__(256, 2)
sgemm_kernel(const float* __restrict__ A, const float* __restrict__ Bm,
             float* __restrict__ C, int M, int N, int K,
             const float* __restrict__ bias,
             const float* __restrict__ scale, const float* __restrict__ shift) {
    __shared__ __align__(16) float As[16][132];
    __shared__ __align__(16) float Bs[16][128];
    int t  = threadIdx.x;
    int m0 = blockIdx.x * 128;
    int n0 = blockIdx.y * 128;
    int tx = t & 15, ty = t >> 4;

    float acc[8][8];
    #pragma unroll
    for (int i = 0; i < 8; i++)
        #pragma unroll
        for (int j = 0; j < 8; j++) acc[i][j] = 0.f;

    int am = t >> 2;           // 0..63
    int ak = (t & 3) * 4;      // 0,4,8,12
    int bk = t >> 5;           // 0..7
    int bn = (t & 31) * 4;

    const float* Aptr = A + (long)(m0 + am) * K + ak;
    const float* Bptr = Bm + (long)bk * N + n0 + bn;

    for (int kt = 0; kt < K; kt += 16) {
        #pragma unroll
        for (int h = 0; h < 2; h++) {
            float4 v = *(const float4*)(Aptr + (long)h * 64 * K + kt);
            if (TRANSA) {
                int kg = kt + ak;
                v.x = fmaxf(0.f, v.x * scale[kg + 0] + shift[kg + 0]);
                v.y = fmaxf(0.f, v.y * scale[kg + 1] + shift[kg + 1]);
                v.z = fmaxf(0.f, v.z * scale[kg + 2] + shift[kg + 2]);
                v.w = fmaxf(0.f, v.w * scale[kg + 3] + shift[kg + 3]);
            }
            As[ak + 0][am + h * 64] = v.x;
            As[ak + 1][am + h * 64] = v.y;
            As[ak + 2][am + h * 64] = v.z;
            As[ak + 3][am + h * 64] = v.w;
        }
        #pragma unroll
        for (int h = 0; h < 2; h++) {
            float4 v = *(const float4*)(Bptr + (long)(kt + h * 8) * N);
            *(float4*)&Bs[bk + h * 8][bn] = v;
        }
        __syncthreads();
        #pragma unroll
        for (int kk = 0; kk < 16; kk++) {
            float4 a0 = *(const float4*)&As[kk][ty * 4];
            float4 a1 = *(const float4*)&As[kk][64 + ty * 4];
            float4 b0 = *(const float4*)&Bs[kk][tx * 4];
            float4 b1 = *(const float4*)&Bs[kk][64 + tx * 4];
            float ar[8] = {a0.x, a0.y, a0.z, a0.w, a1.x, a1.y, a1.z, a1.w};
            float br[8] = {b0.x, b0.y, b0.z, b0.w, b1.x, b1.y, b1.z, b1.w};
            #pragma unroll
            for (int i = 0; i < 8; i++)
                #pragma unroll
                for (int j = 0; j < 8; j++) acc[i][j] += ar[i] * br[j];
        }
        __syncthreads();
    }

    #pragma unroll
    for (int i = 0; i < 8; i++) {
        int row = m0 + ((i < 4) ? (ty * 4 + i) : (64 + ty * 4 + i - 4));
        #pragma unroll
        for (int half = 0; half < 2; half++) {
            int col = n0 + half * 64 + tx * 4;
            float4 v;
            v.x = acc[i][half * 4 + 0];
            v.y = acc[i][half * 4 + 1];
            v.z = acc[i][half * 4 + 2];
            v.w = acc[i][half * 4 + 3];
            if (BIAS) {
                v.x += bias[col + 0]; v.y += bias[col + 1];
                v.z += bias[col + 2]; v.w += bias[col + 3];
            }
            *(float4*)&C[(long)row * N + col] = v;
        }
    }
}

// ---------------- K3: diagonal correction + form [p | q] -------------------
__global__ void combine_kernel(const float* __restrict__ E2,
                               const float* __restrict__ Apar,
                               const float* __restrict__ S,
                               const float* __restrict__ W,
                               float* __restrict__ comb) {
    int b = blockIdx.x, t = threadIdx.x;
    __shared__ float es[FD];
    __shared__ float As[FF];
    #pragma unroll
    for (int r = 0; r < 3; r++) es[t + r * 256] = E2[(long)b * FD + t + r * 256];
    if (t < FF) As[t] = Apar[b * FF + t];
    __syncthreads();
    #pragma unroll
    for (int r = 0; r < 3; r++) {
        int ik = t + r * 256;
        int f = ik >> 5, k = ik & 31;
        const float* wd = W + ((long)(f * FF + f) * DD + k) * DD;  // W[f,f,k,:]
        float dp = 0.f;
        #pragma unroll
        for (int l = 0; l < DD; l++) dp += __ldg(&wd[l]) * es[f * 32 + l];
        float a  = As[f];
        float sp = S[(long)b * FD + ik];
        float sq = S[(long)(BB + b) * FD + ik];
        comb[(long)b * COMB + ik]      = es[ik] * (sp - dp);
        comb[(long)b * COMB + FD + ik] = a * es[ik] * (sq - a * dp);
    }
}

// ---------------- BN stats -> scale/shift ----------------------------------
__global__ void bn_stats_kernel(const float* __restrict__ H, int N,
                                const float* __restrict__ g, const float* __restrict__ be,
                                float* __restrict__ scale, float* __restrict__ shift) {
    int lane = threadIdx.x & 31;
    int ty   = threadIdx.x >> 5;          // 0..15
    int col  = blockIdx.x * 32 + lane;
    float s = 0.f, sq = 0.f;
    for (int r = ty; r < BB; r += 16) {
        float v = H[(long)r * N + col];
        s += v; sq += v * v;
    }
    __shared__ float ss[16][33], sqs[16][33];
    ss[ty][lane] = s; sqs[ty][lane] = sq;
    __syncthreads();
    if (ty == 0) {
        #pragma unroll
        for (int i = 1; i < 16; i++) { s += ss[i][lane]; sq += sqs[i][lane]; }
        float mean = s * (1.f / BB);
        float var  = sq * (1.f / BB) - mean * mean;
        float sc   = g[col] * rsqrtf(var + EPSV);
        scale[col] = sc;
        shift[col] = be[col] - mean * sc;
    }
}

// ---------------- final: BN+ReLU dot w2 + linear + sigmoid -----------------
__global__ void final_kernel(const float* __restrict__ H1,
                             const float* __restrict__ scale, const float* __restrict__ shift,
                             const float* __restrict__ w2, const float* __restrict__ b2,
                             const float* __restrict__ lin, const float* __restrict__ bias0,
                             float* __restrict__ out) {
    int warp = threadIdx.x >> 5, lane = threadIdx.x & 31;
    int row = blockIdx.x * 8 + warp;
    float acc = 0.f;
    #pragma unroll 4
    for (int k = lane; k < H1N; k += 32) {
        float v = H1[(long)row * H1N + k];
        v = fmaxf(0.f, v * scale[k] + shift[k]);
        acc += v * w2[k];
    }
    #pragma unroll
    for (int o = 16; o > 0; o >>= 1) acc += __shfl_xor_sync(0xffffffffu, acc, o);
    if (lane == 0) {
        float logit = acc + b2[0] + lin[row] + bias0[0];
        out[row] = 1.f / (1.f + expf(-logit));
    }
}

// ---------------------------------------------------------------------------
extern "C" void kernel_launch(void* const* d_in, const int* in_sizes, int n_in,
                              void* d_out, int out_size) {
    const int*   x    = (const int*)d_in[0];
    const float* emb  = (const float*)d_in[1];
    const float* lint = (const float*)d_in[2];
    const float* bias = (const float*)d_in[3];
    const float* sw1  = (const float*)d_in[4];
    const float* sw2  = (const float*)d_in[5];
    const float* bilW = (const float*)d_in[6];
    const float* w0   = (const float*)d_in[7];
    const float* b0   = (const float*)d_in[8];
    const float* g0   = (const float*)d_in[9];
    const float* be0  = (const float*)d_in[10];
    const float* w1   = (const float*)d_in[11];
    const float* b1   = (const float*)d_in[12];
    const float* g1   = (const float*)d_in[13];
    const float* be1  = (const float*)d_in[14];
    const float* w2   = (const float*)d_in[15];
    const float* b2   = (const float*)d_in[16];
    float* out = (float*)d_out;

    float *E2, *WT, *S, *comb, *h0, *h1, *Apar, *lin, *sc0, *sh0, *sc1, *sh1;
    cudaGetSymbolAddress((void**)&E2,   g_E2);
    cudaGetSymbolAddress((void**)&WT,   g_WT);
    cudaGetSymbolAddress((void**)&S,    g_S);
    cudaGetSymbolAddress((void**)&comb, g_comb);
    cudaGetSymbolAddress((void**)&h0,   g_h0);
    cudaGetSymbolAddress((void**)&h1,   g_h1);
    cudaGetSymbolAddress((void**)&Apar, g_A);
    cudaGetSymbolAddress((void**)&lin,  g_lin);
    cudaGetSymbolAddress((void**)&sc0,  g_scale0);
    cudaGetSymbolAddress((void**)&sh0,  g_shift0);
    cudaGetSymbolAddress((void**)&sc1,  g_scale1);
    cudaGetSymbolAddress((void**)&sh1,  g_shift1);

    // K0: W -> WT  (768*768 elements)
    transposeW_kernel<<<(FD * FD) / 256, 256>>>(bilW, WT);
    // K1: gather + SENet + linear term
    gather_se_kernel<<<BB, 256>>>(x, emb, lint, sw1, sw2, E2, Apar, lin);
    // G1: S[8192,768] = E2 @ WT
    sgemm_kernel<false, false><<<dim3(2 * BB / 128, FD / 128), 256>>>(
        E2, WT, S, 2 * BB, FD, FD, nullptr, nullptr, nullptr);
    // K3: combined = [p | q]
    combine_kernel<<<BB, 256>>>(E2, Apar, S, bilW, comb);
    // G2: h0 = combined @ w0 + b0
    sgemm_kernel<false, true><<<dim3(BB / 128, H0N / 128), 256>>>(
        comb, w0, h0, BB, H0N, COMB, b0, nullptr, nullptr);
    bn_stats_kernel<<<H0N / 32, 512>>>(h0, H0N, g0, be0, sc0, sh0);
    // G3: h1 = relu(BN(h0)) @ w1 + b1   (BN+ReLU fused into A-load)
    sgemm_kernel<true, true><<<dim3(BB / 128, H1N / 128), 256>>>(
        h0, w1, h1, BB, H1N, H0N, b1, sc0, sh0);
    bn_stats_kernel<<<H1N / 32, 512>>>(h1, H1N, g1, be1, sc1, sh1);
    // final
    final_kernel<<<BB / 8, 256>>>(h1, sc1, sh1, w2, b2, lin, bias, out);
}

// round 2
// speedup vs baseline: 1.5842x; 1.5842x over previous
#include <cuda_runtime.h>
#include <cuda_bf16.h>
#include <math.h>

#define BB   4096
#define FF   24
#define VV   1000
#define DD   32
#define FD   768          // F*D
#define COMB 1536         // 2*F*D
#define H0N  1024
#define H1N  512
#define RED  8
#define EPSV 1e-5f

// ---------------- device scratch (no allocations allowed) ----------------
__device__ __align__(16) float g_E2[2 * BB * FD];     // rows 0..B-1: e, rows B..2B-1: A*e
__device__ __align__(16) float g_WT[FD * FD];         // WT[(j*D+l)*768 + (i*D+k)] = W[i,j,k,l], diag blocks zeroed
__device__ __align__(16) float g_comb[BB * COMB];
__device__ __align__(16) float g_h0[BB * H0N];
__device__ __align__(16) float g_h1[BB * H1N];
__device__ float g_lin[BB];
__device__ float g_scale0[H0N], g_shift0[H0N];
__device__ float g_scale1[H1N], g_shift1[H1N];

// ---------------- K0: rearrange bilinear W into GEMM-B layout --------------
// Diagonal (i==j) blocks are ZEROED so the GEMM directly computes sum_{j!=i}.
__global__ void transposeW_kernel(const float* __restrict__ W, float* __restrict__ WT) {
    int o = blockIdx.x * 256 + threadIdx.x;      // o in [0, 768*768)
    int ik = o % FD, jl = o / FD;
    int i = ik >> 5, k = ik & 31, j = jl >> 5, l = jl & 31;
    WT[o] = (i == j) ? 0.f : W[(((i * FF + j) * DD + k) * DD) + l];
}

// ---------------- K1: gather + linear + SENet -----------------------------
__global__ void gather_se_kernel(const int* __restrict__ x,
                                 const float* __restrict__ emb,
                                 const float* __restrict__ lint,
                                 const float* __restrict__ sw1,
                                 const float* __restrict__ sw2,
                                 float* __restrict__ E2,
                                 float* __restrict__ linout) {
    int b = blockIdx.x;
    int t = threadIdx.x;
    __shared__ int   xs[FF];
    __shared__ float es[FD];
    __shared__ float Zs[FF], hid[RED], As[FF], linp[FF];

    if (t < FF) xs[t] = x[b * FF + t];
    __syncthreads();

    #pragma unroll
    for (int r = 0; r < 3; r++) {
        int ik = t + r * 256;
        int f = ik >> 5, d = ik & 31;
        es[ik] = emb[((long)f * VV + xs[f]) * DD + d];
    }
    if (t < FF) linp[t] = lint[(long)t * VV + xs[t]];
    __syncthreads();

    // squeeze: mean over D per field (warp w -> fields 3w..3w+2)
    int w = t >> 5, lane = t & 31;
    #pragma unroll
    for (int ff = 0; ff < 3; ff++) {
        int f = w * 3 + ff;
        float v = es[f * 32 + lane];
        #pragma unroll
        for (int o = 16; o > 0; o >>= 1) v += __shfl_xor_sync(0xffffffffu, v, o);
        if (lane == 0) Zs[f] = v * (1.f / 32.f);
    }
    __syncthreads();
    if (t < RED) {
        float s = 0.f;
        #pragma unroll
        for (int f = 0; f < FF; f++) s += Zs[f] * sw1[t * FF + f];
        hid[t] = fmaxf(s, 0.f);
    }
    __syncthreads();
    if (t < FF) {
        float s = 0.f;
        #pragma unroll
        for (int r = 0; r < RED; r++) s += hid[r] * sw2[t * RED + r];
        As[t] = 1.f / (1.f + expf(-s));
    }
    if (t == 0) {
        float s = 0.f;
        #pragma unroll
        for (int f = 0; f < FF; f++) s += linp[f];
        linout[b] = s;
    }
    __syncthreads();

    #pragma unroll
    for (int r = 0; r < 3; r++) {
        int ik = t + r * 256;
        int f = ik >> 5;
        float e = es[ik];
        E2[(long)b * FD + ik] = e;
        E2[(long)(BB + b) * FD + ik] = As[f] * e;
    }
}

// ---------------- generic 128x128x16 SGEMM, register double-buffered ------
// Modes:
//   TRANSA:  A columns get BN (scale/shift) + ReLU on load
//   BIAS:    add bias[n] in epilogue
//   COMBINE: epilogue computes val *= E2[m,n] and scatters into comb with
//            [p|q] layout: m<BB -> comb[m*COMB + n]; m>=BB -> comb[(m-BB)*COMB + FD + n]
template <bool TRANSA, bool BIAS, bool COMBINE>
__global__ void __launch_bounds__(256, 2)
sgemm_kernel(const float* __restrict__ A, const float* __restrict__ Bm,
             float* __restrict__ C, int M, int N, int K,
             const float* __restrict__ bias,
             const float* __restrict__ scale, const float* __restrict__ shift,
             const float* __restrict__ E2) {
    __shared__ __align__(16) float As[16][132];
    __shared__ __align__(16) float Bs[16][128];
    int t  = threadIdx.x;
    int m0 = blockIdx.x * 128;
    int n0 = blockIdx.y * 128;
    int tx = t & 15, ty = t >> 4;

    float acc[8][8];
    #pragma unroll
    for (int i = 0; i < 8; i++)
        #pragma unroll
        for (int j = 0; j < 8; j++) acc[i][j] = 0.f;

    int am = t >> 2;           // 0..63
    int ak = (t & 3) * 4;      // 0,4,8,12
    int bk = t >> 5;           // 0..7
    int bn = (t & 31) * 4;

    const float* Aptr = A + (long)(m0 + am) * K + ak;
    const float* Bptr = Bm + (long)bk * N + n0 + bn;

    float4 ra[2], rb[2];
    #pragma unroll
    for (int h = 0; h < 2; h++) {
        ra[h] = *(const float4*)(Aptr + (long)h * 64 * K);
        rb[h] = *(const float4*)(Bptr + (long)h * 8 * N);
    }

    for (int kt = 0; kt < K; kt += 16) {
        // stage current regs -> smem (apply BN+ReLU to A if requested)
        #pragma unroll
        for (int h = 0; h < 2; h++) {
            float4 v = ra[h];
            if (TRANSA) {
                int kg = kt + ak;
                v.x = fmaxf(0.f, v.x * scale[kg + 0] + shift[kg + 0]);
                v.y = fmaxf(0.f, v.y * scale[kg + 1] + shift[kg + 1]);
                v.z = fmaxf(0.f, v.z * scale[kg + 2] + shift[kg + 2]);
                v.w = fmaxf(0.f, v.w * scale[kg + 3] + shift[kg + 3]);
            }
            As[ak + 0][am + h * 64] = v.x;
            As[ak + 1][am + h * 64] = v.y;
            As[ak + 2][am + h * 64] = v.z;
            As[ak + 3][am + h * 64] = v.w;
            *(float4*)&Bs[bk + h * 8][bn] = rb[h];
        }
        __syncthreads();
        // prefetch next tile while computing this one
        if (kt + 16 < K) {
            #pragma unroll
            for (int h = 0; h < 2; h++) {
                ra[h] = *(const float4*)(Aptr + (long)h * 64 * K + kt + 16);
                rb[h] = *(const float4*)(Bptr + (long)(kt + 16 + h * 8) * N);
            }
        }
        #pragma unroll
        for (int kk = 0; kk < 16; kk++) {
            float4 a0 = *(const float4*)&As[kk][ty * 4];
            float4 a1 = *(const float4*)&As[kk][64 + ty * 4];
            float4 b0 = *(const float4*)&Bs[kk][tx * 4];
            float4 b1 = *(const float4*)&Bs[kk][64 + tx * 4];
            float ar[8] = {a0.x, a0.y, a0.z, a0.w, a1.x, a1.y, a1.z, a1.w};
            float br[8] = {b0.x, b0.y, b0.z, b0.w, b1.x, b1.y, b1.z, b1.w};
            #pragma unroll
            for (int i = 0; i < 8; i++)
                #pragma unroll
                for (int j = 0; j < 8; j++) acc[i][j] += ar[i] * br[j];
        }
        __syncthreads();
    }

    #pragma unroll
    for (int i = 0; i < 8; i++) {
        int row = m0 + ((i < 4) ? (ty * 4 + i) : (64 + ty * 4 + i - 4));
        #pragma unroll
        for (int half = 0; half < 2; half++) {
            int col = n0 + half * 64 + tx * 4;
            float4 v;
            v.x = acc[i][half * 4 + 0];
            v.y = acc[i][half * 4 + 1];
            v.z = acc[i][half * 4 + 2];
            v.w = acc[i][half * 4 + 3];
            if (BIAS) {
                v.x += bias[col + 0]; v.y += bias[col + 1];
                v.z += bias[col + 2]; v.w += bias[col + 3];
            }
            if (COMBINE) {
                float4 e = *(const float4*)&E2[(long)row * FD + col];
                v.x *= e.x; v.y *= e.y; v.z *= e.z; v.w *= e.w;
                long brow = (row < BB) ? row : (row - BB);
                int  coff = (row < BB) ? 0 : FD;
                *(float4*)&C[brow * (long)COMB + coff + col] = v;
            } else {
                *(float4*)&C[(long)row * N + col] = v;
            }
        }
    }
}

// ---------------- BN stats -> scale/shift ----------------------------------
__global__ void bn_stats_kernel(const float* __restrict__ H, int N,
                                const float* __restrict__ g, const float* __restrict__ be,
                                float* __restrict__ scale, float* __restrict__ shift) {
    int lane = threadIdx.x & 31;
    int ty   = threadIdx.x >> 5;          // 0..15
    int col  = blockIdx.x * 32 + lane;
    float s = 0.f, sq = 0.f;
    for (int r = ty; r < BB; r += 16) {
        float v = H[(long)r * N + col];
        s += v; sq += v * v;
    }
    __shared__ float ss[16][33], sqs[16][33];
    ss[ty][lane] = s; sqs[ty][lane] = sq;
    __syncthreads();
    if (ty == 0) {
        #pragma unroll
        for (int i = 1; i < 16; i++) { s += ss[i][lane]; sq += sqs[i][lane]; }
        float mean = s * (1.f / BB);
        float var  = sq * (1.f / BB) - mean * mean;
        float sc   = g[col] * rsqrtf(var + EPSV);
        scale[col] = sc;
        shift[col] = be[col] - mean * sc;
    }
}

// ---------------- final: BN+ReLU dot w2 + linear + sigmoid -----------------
__global__ void final_kernel(const float* __restrict__ H1,
                             const float* __restrict__ scale, const float* __restrict__ shift,
                             const float* __restrict__ w2, const float* __restrict__ b2,
                             const float* __restrict__ lin, const float* __restrict__ bias0,
                             float* __restrict__ out) {
    int warp = threadIdx.x >> 5, lane = threadIdx.x & 31;
    int row = blockIdx.x * 8 + warp;
    float acc = 0.f;
    #pragma unroll 4
    for (int k = lane; k < H1N; k += 32) {
        float v = H1[(long)row * H1N + k];
        v = fmaxf(0.f, v * scale[k] + shift[k]);
        acc += v * w2[k];
    }
    #pragma unroll
    for (int o = 16; o > 0; o >>= 1) acc += __shfl_xor_sync(0xffffffffu, acc, o);
    if (lane == 0) {
        float logit = acc + b2[0] + lin[row] + bias0[0];
        out[row] = 1.f / (1.f + expf(-logit));
    }
}

// ---------------------------------------------------------------------------
extern "C" void kernel_launch(void* const* d_in, const int* in_sizes, int n_in,
                              void* d_out, int out_size) {
    const int*   x    = (const int*)d_in[0];
    const float* emb  = (const float*)d_in[1];
    const float* lint = (const float*)d_in[2];
    const float* bias = (const float*)d_in[3];
    const float* sw1  = (const float*)d_in[4];
    const float* sw2  = (const float*)d_in[5];
    const float* bilW = (const float*)d_in[6];
    const float* w0   = (const float*)d_in[7];
    const float* b0   = (const float*)d_in[8];
    const float* g0   = (const float*)d_in[9];
    const float* be0  = (const float*)d_in[10];
    const float* w1   = (const float*)d_in[11];
    const float* b1   = (const float*)d_in[12];
    const float* g1   = (const float*)d_in[13];
    const float* be1  = (const float*)d_in[14];
    const float* w2   = (const float*)d_in[15];
    const float* b2   = (const float*)d_in[16];
    float* out = (float*)d_out;

    float *E2, *WT, *comb, *h0, *h1, *lin, *sc0, *sh0, *sc1, *sh1;
    cudaGetSymbolAddress((void**)&E2,   g_E2);
    cudaGetSymbolAddress((void**)&WT,   g_WT);
    cudaGetSymbolAddress((void**)&comb, g_comb);
    cudaGetSymbolAddress((void**)&h0,   g_h0);
    cudaGetSymbolAddress((void**)&h1,   g_h1);
    cudaGetSymbolAddress((void**)&lin,  g_lin);
    cudaGetSymbolAddress((void**)&sc0,  g_scale0);
    cudaGetSymbolAddress((void**)&sh0,  g_shift0);
    cudaGetSymbolAddress((void**)&sc1,  g_scale1);
    cudaGetSymbolAddress((void**)&sh1,  g_shift1);

    // K0: W -> WT with diagonal blocks zeroed
    transposeW_kernel<<<(FD * FD) / 256, 256>>>(bilW, WT);
    // K1: gather + SENet + linear term
    gather_se_kernel<<<BB, 256>>>(x, emb, lint, sw1, sw2, E2, lin);
    // G1: comb = (E2 @ WT) * E2, scattered into [p|q] layout (S never materialized)
    sgemm_kernel<false, false, true><<<dim3(2 * BB / 128, FD / 128), 256>>>(
        E2, WT, comb, 2 * BB, FD, FD, nullptr, nullptr, nullptr, E2);
    // G2: h0 = comb @ w0 + b0
    sgemm_kernel<false, true, false><<<dim3(BB / 128, H0N / 128), 256>>>(
        comb, w0, h0, BB, H0N, COMB, b0, nullptr, nullptr, nullptr);
    bn_stats_kernel<<<H0N / 32, 512>>>(h0, H0N, g0, be0, sc0, sh0);
    // G3: h1 = relu(BN(h0)) @ w1 + b1   (BN+ReLU fused into A-load)
    sgemm_kernel<true, true, false><<<dim3(BB / 128, H1N / 128), 256>>>(
        h0, w1, h1, BB, H1N, H0N, b1, sc0, sh0, nullptr);
    bn_stats_kernel<<<H1N / 32, 512>>>(h1, H1N, g1, be1, sc1, sh1);
    // final
    final_kernel<<<BB / 8, 256>>>(h1, sc1, sh1, w2, b2, lin, bias, out);
}

// round 3
// speedup vs baseline: 3.0661x; 1.9354x over previous
#include <cuda_runtime.h>
#include <cuda_bf16.h>
#include <math.h>

#define BB   4096
#define FF   24
#define VV   1000
#define DD   32
#define FD   768          // F*D
#define COMB 1536         // 2*F*D
#define H0N  1024
#define H1N  512
#define RED  8
#define EPSV 1e-5f

// ---------------- device scratch (no allocations allowed) ----------------
__device__ __align__(16) float g_E2[2 * BB * FD];     // rows 0..B-1: e, rows B..2B-1: A*e
__device__ __align__(16) float g_WT[FD * FD];         // WT[(j*D+l)*768 + (i*D+k)] = W[i,j,k,l], diag zeroed
__device__ __align__(16) float g_comb[BB * COMB];
__device__ __align__(16) float g_h0[BB * H0N];
__device__ __align__(16) float g_h1[BB * H1N];
__device__ float g_lin[BB];
__device__ float g_scale0[H0N], g_shift0[H0N];
__device__ float g_scale1[H1N], g_shift1[H1N];

#define CVT_TF32(u, f) asm("cvt.rna.tf32.f32 %0, %1;" : "=r"(u) : "f"(f))

// ---------------- K0: rearrange bilinear W into GEMM-B layout --------------
__global__ void transposeW_kernel(const float* __restrict__ W, float* __restrict__ WT) {
    int o = blockIdx.x * 256 + threadIdx.x;      // o in [0, 768*768)
    int ik = o % FD, jl = o / FD;
    int i = ik >> 5, k = ik & 31, j = jl >> 5, l = jl & 31;
    WT[o] = (i == j) ? 0.f : W[(((i * FF + j) * DD + k) * DD) + l];
}

// ---------------- K1: gather + linear + SENet -----------------------------
__global__ void gather_se_kernel(const int* __restrict__ x,
                                 const float* __restrict__ emb,
                                 const float* __restrict__ lint,
                                 const float* __restrict__ sw1,
                                 const float* __restrict__ sw2,
                                 float* __restrict__ E2,
                                 float* __restrict__ linout) {
    int b = blockIdx.x;
    int t = threadIdx.x;
    __shared__ int   xs[FF];
    __shared__ float es[FD];
    __shared__ float Zs[FF], hid[RED], As[FF], linp[FF];

    if (t < FF) xs[t] = x[b * FF + t];
    __syncthreads();

    #pragma unroll
    for (int r = 0; r < 3; r++) {
        int ik = t + r * 256;
        int f = ik >> 5, d = ik & 31;
        es[ik] = emb[((long)f * VV + xs[f]) * DD + d];
    }
    if (t < FF) linp[t] = lint[(long)t * VV + xs[t]];
    __syncthreads();

    int w = t >> 5, lane = t & 31;
    #pragma unroll
    for (int ff = 0; ff < 3; ff++) {
        int f = w * 3 + ff;
        float v = es[f * 32 + lane];
        #pragma unroll
        for (int o = 16; o > 0; o >>= 1) v += __shfl_xor_sync(0xffffffffu, v, o);
        if (lane == 0) Zs[f] = v * (1.f / 32.f);
    }
    __syncthreads();
    if (t < RED) {
        float s = 0.f;
        #pragma unroll
        for (int f = 0; f < FF; f++) s += Zs[f] * sw1[t * FF + f];
        hid[t] = fmaxf(s, 0.f);
    }
    __syncthreads();
    if (t < FF) {
        float s = 0.f;
        #pragma unroll
        for (int r = 0; r < RED; r++) s += hid[r] * sw2[t * RED + r];
        As[t] = 1.f / (1.f + expf(-s));
    }
    if (t == 0) {
        float s = 0.f;
        #pragma unroll
        for (int f = 0; f < FF; f++) s += linp[f];
        linout[b] = s;
    }
    __syncthreads();

    #pragma unroll
    for (int r = 0; r < 3; r++) {
        int ik = t + r * 256;
        int f = ik >> 5;
        float e = es[ik];
        E2[(long)b * FD + ik] = e;
        E2[(long)(BB + b) * FD + ik] = As[f] * e;
    }
}

// ---------------- tf32 tensor-core GEMM, 128x128x16 tiles ------------------
// 256 thr = 8 warps in 2(m) x 4(n); each warp computes 64x32 via m16n8k8 mma.
// Modes: TRANSA = BN+ReLU on A columns at load; BIAS; COMBINE (mult by E2 and
// scatter into [p|q] layout of comb).
template <bool TRANSA, bool BIAS, bool COMBINE>
__global__ void __launch_bounds__(256, 2)
tf32gemm_kernel(const float* __restrict__ A, const float* __restrict__ Bm,
                float* __restrict__ C, int M, int N, int K,
                const float* __restrict__ bias,
                const float* __restrict__ scale, const float* __restrict__ shift,
                const float* __restrict__ E2) {
    __shared__ __align__(16) unsigned As[128][20];   // [m][k], pad->20 (conflict-free frag reads)
    __shared__ __align__(16) unsigned Bs[16][136];   // [k][n], pad->136

    int t = threadIdx.x;
    int m0 = blockIdx.x * 128, n0 = blockIdx.y * 128;
    int wid = t >> 5, lane = t & 31;
    int wm = (wid & 1) * 64, wn = (wid >> 1) * 32;
    int r = lane >> 2, quad = lane & 3;

    float acc[4][4][4];
    #pragma unroll
    for (int mi = 0; mi < 4; mi++)
        #pragma unroll
        for (int ni = 0; ni < 4; ni++)
            #pragma unroll
            for (int c = 0; c < 4; c++) acc[mi][ni][c] = 0.f;

    int am = t >> 2;            // 0..63 (two halves)
    int ak = (t & 3) * 4;       // 0,4,8,12
    int bk = t >> 5;            // 0..7 (two halves)
    int bn = (t & 31) * 4;

    const float* Aptr = A + (long)(m0 + am) * K + ak;
    const float* Bptr = Bm + (long)bk * N + n0 + bn;

    float4 ra[2], rb[2];
    #pragma unroll
    for (int h = 0; h < 2; h++) {
        ra[h] = *(const float4*)(Aptr + (long)h * 64 * K);
        rb[h] = *(const float4*)(Bptr + (long)h * 8 * N);
    }

    for (int kt = 0; kt < K; kt += 16) {
        // stage regs -> smem with tf32 rounding (+BN/ReLU on A if TRANSA)
        #pragma unroll
        for (int h = 0; h < 2; h++) {
            float4 v = ra[h];
            if (TRANSA) {
                int kg = kt + ak;
                v.x = fmaxf(0.f, v.x * scale[kg + 0] + shift[kg + 0]);
                v.y = fmaxf(0.f, v.y * scale[kg + 1] + shift[kg + 1]);
                v.z = fmaxf(0.f, v.z * scale[kg + 2] + shift[kg + 2]);
                v.w = fmaxf(0.f, v.w * scale[kg + 3] + shift[kg + 3]);
            }
            uint4 u;
            CVT_TF32(u.x, v.x); CVT_TF32(u.y, v.y);
            CVT_TF32(u.z, v.z); CVT_TF32(u.w, v.w);
            *(uint4*)&As[am + h * 64][ak] = u;
            float4 w4 = rb[h];
            uint4 ub;
            CVT_TF32(ub.x, w4.x); CVT_TF32(ub.y, w4.y);
            CVT_TF32(ub.z, w4.z); CVT_TF32(ub.w, w4.w);
            *(uint4*)&Bs[bk + h * 8][bn] = ub;
        }
        __syncthreads();
        if (kt + 16 < K) {
            #pragma unroll
            for (int h = 0; h < 2; h++) {
                ra[h] = *(const float4*)(Aptr + (long)h * 64 * K + kt + 16);
                rb[h] = *(const float4*)(Bptr + (long)(kt + 16 + h * 8) * N);
            }
        }
        #pragma unroll
        for (int ks = 0; ks < 16; ks += 8) {
            unsigned a[4][4];
            #pragma unroll
            for (int mi = 0; mi < 4; mi++) {
                int mrow = wm + mi * 16 + r;
                a[mi][0] = As[mrow    ][ks + quad];
                a[mi][1] = As[mrow + 8][ks + quad];
                a[mi][2] = As[mrow    ][ks + quad + 4];
                a[mi][3] = As[mrow + 8][ks + quad + 4];
            }
            unsigned b[4][2];
            #pragma unroll
            for (int ni = 0; ni < 4; ni++) {
                int ncol = wn + ni * 8 + r;
                b[ni][0] = Bs[ks + quad    ][ncol];
                b[ni][1] = Bs[ks + quad + 4][ncol];
            }
            #pragma unroll
            for (int mi = 0; mi < 4; mi++)
                #pragma unroll
                for (int ni = 0; ni < 4; ni++) {
                    asm volatile(
                        "mma.sync.aligned.m16n8k8.row.col.f32.tf32.tf32.f32 "
                        "{%0,%1,%2,%3}, {%4,%5,%6,%7}, {%8,%9}, {%0,%1,%2,%3};"
                        : "+f"(acc[mi][ni][0]), "+f"(acc[mi][ni][1]),
                          "+f"(acc[mi][ni][2]), "+f"(acc[mi][ni][3])
                        : "r"(a[mi][0]), "r"(a[mi][1]), "r"(a[mi][2]), "r"(a[mi][3]),
                          "r"(b[ni][0]), "r"(b[ni][1]));
                }
        }
        __syncthreads();
    }

    // epilogue
    #pragma unroll
    for (int mi = 0; mi < 4; mi++) {
        #pragma unroll
        for (int ni = 0; ni < 4; ni++) {
            int row0 = m0 + wm + mi * 16 + r;
            int row1 = row0 + 8;
            int col  = n0 + wn + ni * 8 + 2 * quad;
            float2 v0 = make_float2(acc[mi][ni][0], acc[mi][ni][1]);
            float2 v1 = make_float2(acc[mi][ni][2], acc[mi][ni][3]);
            if (BIAS) {
                float b0v = bias[col], b1v = bias[col + 1];
                v0.x += b0v; v0.y += b1v;
                v1.x += b0v; v1.y += b1v;
            }
            if (COMBINE) {
                float2 e0 = *(const float2*)&E2[(long)row0 * FD + col];
                float2 e1 = *(const float2*)&E2[(long)row1 * FD + col];
                v0.x *= e0.x; v0.y *= e0.y;
                v1.x *= e1.x; v1.y *= e1.y;
                long br0 = (row0 < BB) ? row0 : (row0 - BB);
                long br1 = (row1 < BB) ? row1 : (row1 - BB);
                int  c0  = (row0 < BB) ? 0 : FD;
                int  c1  = (row1 < BB) ? 0 : FD;
                *(float2*)&C[br0 * (long)COMB + c0 + col] = v0;
                *(float2*)&C[br1 * (long)COMB + c1 + col] = v1;
            } else {
                *(float2*)&C[(long)row0 * N + col] = v0;
                *(float2*)&C[(long)row1 * N + col] = v1;
            }
        }
    }
}

// ---------------- BN stats -> scale/shift ----------------------------------
__global__ void bn_stats_kernel(const float* __restrict__ H, int N,
                                const float* __restrict__ g, const float* __restrict__ be,
                                float* __restrict__ scale, float* __restrict__ shift) {
    int lane = threadIdx.x & 31;
    int ty   = threadIdx.x >> 5;          // 0..15
    int col  = blockIdx.x * 32 + lane;
    float s = 0.f, sq = 0.f;
    for (int r = ty; r < BB; r += 16) {
        float v = H[(long)r * N + col];
        s += v; sq += v * v;
    }
    __shared__ float ss[16][33], sqs[16][33];
    ss[ty][lane] = s; sqs[ty][lane] = sq;
    __syncthreads();
    if (ty == 0) {
        #pragma unroll
        for (int i = 1; i < 16; i++) { s += ss[i][lane]; sq += sqs[i][lane]; }
        float mean = s * (1.f / BB);
        float var  = sq * (1.f / BB) - mean * mean;
        float sc   = g[col] * rsqrtf(var + EPSV);
        scale[col] = sc;
        shift[col] = be[col] - mean * sc;
    }
}

// ---------------- final: BN+ReLU dot w2 + linear + sigmoid -----------------
__global__ void final_kernel(const float* __restrict__ H1,
                             const float* __restrict__ scale, const float* __restrict__ shift,
                             const float* __restrict__ w2, const float* __restrict__ b2,
                             const float* __restrict__ lin, const float* __restrict__ bias0,
                             float* __restrict__ out) {
    int warp = threadIdx.x >> 5, lane = threadIdx.x & 31;
    int row = blockIdx.x * 8 + warp;
    float acc = 0.f;
    #pragma unroll 4
    for (int k = lane; k < H1N; k += 32) {
        float v = H1[(long)row * H1N + k];
        v = fmaxf(0.f, v * scale[k] + shift[k]);
        acc += v * w2[k];
    }
    #pragma unroll
    for (int o = 16; o > 0; o >>= 1) acc += __shfl_xor_sync(0xffffffffu, acc, o);
    if (lane == 0) {
        float logit = acc + b2[0] + lin[row] + bias0[0];
        out[row] = 1.f / (1.f + expf(-logit));
    }
}

// ---------------------------------------------------------------------------
extern "C" void kernel_launch(void* const* d_in, const int* in_sizes, int n_in,
                              void* d_out, int out_size) {
    const int*   x    = (const int*)d_in[0];
    const float* emb  = (const float*)d_in[1];
    const float* lint = (const float*)d_in[2];
    const float* bias = (const float*)d_in[3];
    const float* sw1  = (const float*)d_in[4];
    const float* sw2  = (const float*)d_in[5];
    const float* bilW = (const float*)d_in[6];
    const float* w0   = (const float*)d_in[7];
    const float* b0   = (const float*)d_in[8];
    const float* g0   = (const float*)d_in[9];
    const float* be0  = (const float*)d_in[10];
    const float* w1   = (const float*)d_in[11];
    const float* b1   = (const float*)d_in[12];
    const float* g1   = (const float*)d_in[13];
    const float* be1  = (const float*)d_in[14];
    const float* w2   = (const float*)d_in[15];
    const float* b2   = (const float*)d_in[16];
    float* out = (float*)d_out;

    float *E2, *WT, *comb, *h0, *h1, *lin, *sc0, *sh0, *sc1, *sh1;
    cudaGetSymbolAddress((void**)&E2,   g_E2);
    cudaGetSymbolAddress((void**)&WT,   g_WT);
    cudaGetSymbolAddress((void**)&comb, g_comb);
    cudaGetSymbolAddress((void**)&h0,   g_h0);
    cudaGetSymbolAddress((void**)&h1,   g_h1);
    cudaGetSymbolAddress((void**)&lin,  g_lin);
    cudaGetSymbolAddress((void**)&sc0,  g_scale0);
    cudaGetSymbolAddress((void**)&sh0,  g_shift0);
    cudaGetSymbolAddress((void**)&sc1,  g_scale1);
    cudaGetSymbolAddress((void**)&sh1,  g_shift1);

    // K0: W -> WT with diagonal blocks zeroed
    transposeW_kernel<<<(FD * FD) / 256, 256>>>(bilW, WT);
    // K1: gather + SENet + linear term
    gather_se_kernel<<<BB, 256>>>(x, emb, lint, sw1, sw2, E2, lin);
    // G1: comb = (E2 @ WT) * E2 scattered into [p|q] layout
    tf32gemm_kernel<false, false, true><<<dim3(2 * BB / 128, FD / 128), 256>>>(
        E2, WT, comb, 2 * BB, FD, FD, nullptr, nullptr, nullptr, E2);
    // G2: h0 = comb @ w0 + b0
    tf32gemm_kernel<false, true, false><<<dim3(BB / 128, H0N / 128), 256>>>(
        comb, w0, h0, BB, H0N, COMB, b0, nullptr, nullptr, nullptr);
    bn_stats_kernel<<<H0N / 32, 512>>>(h0, H0N, g0, be0, sc0, sh0);
    // G3: h1 = relu(BN(h0)) @ w1 + b1   (BN+ReLU fused into A-load)
    tf32gemm_kernel<true, true, false><<<dim3(BB / 128, H1N / 128), 256>>>(
        h0, w1, h1, BB, H1N, H0N, b1, sc0, sh0, nullptr);
    bn_stats_kernel<<<H1N / 32, 512>>>(h1, H1N, g1, be1, sc1, sh1);
    // final
    final_kernel<<<BB / 8, 256>>>(h1, sc1, sh1, w2, b2, lin, bias, out);
}

// round 4
// speedup vs baseline: 3.4489x; 1.1249x over previous
#include <cuda_runtime.h>
#include <cuda_bf16.h>
#include <math.h>

#define BB   4096
#define FF   24
#define VV   1000
#define DD   32
#define FD   768          // F*D
#define COMB 1536         // 2*F*D
#define H0N  1024
#define H1N  512
#define RED  8
#define EPSV 1e-5f

// ---------------- device scratch (no allocations allowed) ----------------
__device__ __align__(16) float g_E2[2 * BB * FD];
__device__ __align__(16) float g_WT[FD * FD];
__device__ __align__(16) float g_comb[BB * COMB];
__device__ __align__(16) float g_h0[BB * H0N];
__device__ __align__(16) float g_h1[BB * H1N];
__device__ float g_lin[BB];
__device__ float g_scale0[H0N], g_shift0[H0N];
__device__ float g_scale1[H1N], g_shift1[H1N];

#define CVT_TF32(u, f) asm("cvt.rna.tf32.f32 %0, %1;" : "=r"(u) : "f"(f))

// swizzled A smem offset (4B units): row stride 16, 16B-chunk XOR swizzle
__device__ __forceinline__ int a_off(int m, int c) {
    return m * 16 + ((((c >> 2) ^ (m >> 1)) & 3) << 2) + (c & 3);
}

// ---------------- K0: rearrange bilinear W into GEMM-B layout --------------
__global__ void transposeW_kernel(const float* __restrict__ W, float* __restrict__ WT) {
    int o = blockIdx.x * 256 + threadIdx.x;
    int ik = o % FD, jl = o / FD;
    int i = ik >> 5, k = ik & 31, j = jl >> 5, l = jl & 31;
    WT[o] = (i == j) ? 0.f : W[(((i * FF + j) * DD + k) * DD) + l];
}

// ---------------- K1: gather + linear + SENet -----------------------------
__global__ void gather_se_kernel(const int* __restrict__ x,
                                 const float* __restrict__ emb,
                                 const float* __restrict__ lint,
                                 const float* __restrict__ sw1,
                                 const float* __restrict__ sw2,
                                 float* __restrict__ E2,
                                 float* __restrict__ linout) {
    int b = blockIdx.x;
    int t = threadIdx.x;
    __shared__ int   xs[FF];
    __shared__ float es[FD];
    __shared__ float Zs[FF], hid[RED], As[FF], linp[FF];

    if (t < FF) xs[t] = x[b * FF + t];
    __syncthreads();

    #pragma unroll
    for (int r = 0; r < 3; r++) {
        int ik = t + r * 256;
        int f = ik >> 5, d = ik & 31;
        es[ik] = emb[((long)f * VV + xs[f]) * DD + d];
    }
    if (t < FF) linp[t] = lint[(long)t * VV + xs[t]];
    __syncthreads();

    int w = t >> 5, lane = t & 31;
    #pragma unroll
    for (int ff = 0; ff < 3; ff++) {
        int f = w * 3 + ff;
        float v = es[f * 32 + lane];
        #pragma unroll
        for (int o = 16; o > 0; o >>= 1) v += __shfl_xor_sync(0xffffffffu, v, o);
        if (lane == 0) Zs[f] = v * (1.f / 32.f);
    }
    __syncthreads();
    if (t < RED) {
        float s = 0.f;
        #pragma unroll
        for (int f = 0; f < FF; f++) s += Zs[f] * sw1[t * FF + f];
        hid[t] = fmaxf(s, 0.f);
    }
    __syncthreads();
    if (t < FF) {
        float s = 0.f;
        #pragma unroll
        for (int r = 0; r < RED; r++) s += hid[r] * sw2[t * RED + r];
        As[t] = 1.f / (1.f + expf(-s));
    }
    if (t == 0) {
        float s = 0.f;
        #pragma unroll
        for (int f = 0; f < FF; f++) s += linp[f];
        linout[b] = s;
    }
    __syncthreads();

    #pragma unroll
    for (int r = 0; r < 3; r++) {
        int ik = t + r * 256;
        int f = ik >> 5;
        float e = es[ik];
        E2[(long)b * FD + ik] = e;
        E2[(long)(BB + b) * FD + ik] = As[f] * e;
    }
}

// ---------------- tf32 tensor-core GEMM v2 --------------------------------
// 128 threads = 4 warps (2x2); block tile 128x128; warp tile 64x64; K-tile 16.
// Double-buffered smem; swizzled A layout (STS.128 staging, conflict-free LDS);
// B layout [k][136] (conflict-free both ways).
template <bool TRANSA, bool BIAS, bool COMBINE>
__global__ void __launch_bounds__(128, 2)
tf32gemm_kernel(const float* __restrict__ A, const float* __restrict__ Bm,
                float* __restrict__ C, int M, int N, int K,
                const float* __restrict__ bias,
                const float* __restrict__ scale, const float* __restrict__ shift,
                const float* __restrict__ E2) {
    __shared__ __align__(16) unsigned Asm[2][128 * 16];
    __shared__ __align__(16) unsigned Bsm[2][16][136];

    int t = threadIdx.x;
    int m0 = blockIdx.x * 128, n0 = blockIdx.y * 128;
    int wid = t >> 5, lane = t & 31;
    int wm = (wid & 1) * 64, wn = (wid >> 1) * 64;
    int r = lane >> 2, quad = lane & 3;

    float acc[4][8][4];
    #pragma unroll
    for (int mi = 0; mi < 4; mi++)
        #pragma unroll
        for (int ni = 0; ni < 8; ni++)
            #pragma unroll
            for (int c = 0; c < 4; c++) acc[mi][ni][c] = 0.f;

    int am = t >> 2;          // 0..31
    int ak = (t & 3) * 4;     // 0,4,8,12
    int bk = t >> 5;          // 0..3
    int bn = (t & 31) * 4;

    const float* Aptr = A + (long)(m0 + am) * K + ak;
    const float* Bptr = Bm + (long)bk * N + n0 + bn;

    float4 ra[4], rb[4];
    #pragma unroll
    for (int h = 0; h < 4; h++) {
        ra[h] = *(const float4*)(Aptr + (long)h * 32 * K);
        rb[h] = *(const float4*)(Bptr + (long)h * 4 * N);
    }

    // ---- stage tile kt=0 into buffer 0 ----
    #pragma unroll
    for (int h = 0; h < 4; h++) {
        float4 v = ra[h];
        if (TRANSA) {
            int kg = 0 + ak;
            v.x = fmaxf(0.f, v.x * scale[kg + 0] + shift[kg + 0]);
            v.y = fmaxf(0.f, v.y * scale[kg + 1] + shift[kg + 1]);
            v.z = fmaxf(0.f, v.z * scale[kg + 2] + shift[kg + 2]);
            v.w = fmaxf(0.f, v.w * scale[kg + 3] + shift[kg + 3]);
        }
        uint4 u;
        CVT_TF32(u.x, v.x); CVT_TF32(u.y, v.y); CVT_TF32(u.z, v.z); CVT_TF32(u.w, v.w);
        int m = am + h * 32;
        int ck = (((ak >> 2) ^ (m >> 1)) & 3) << 2;
        *(uint4*)&Asm[0][m * 16 + ck] = u;
        float4 w4 = rb[h];
        uint4 ub;
        CVT_TF32(ub.x, w4.x); CVT_TF32(ub.y, w4.y); CVT_TF32(ub.z, w4.z); CVT_TF32(ub.w, w4.w);
        *(uint4*)&Bsm[0][bk + h * 4][bn] = ub;
    }
    __syncthreads();

    int buf = 0;
    for (int kt = 0; kt < K; kt += 16) {
        bool more = (kt + 16) < K;
        if (more) {
            #pragma unroll
            for (int h = 0; h < 4; h++) {
                ra[h] = *(const float4*)(Aptr + (long)h * 32 * K + kt + 16);
                rb[h] = *(const float4*)(Bptr + (long)(kt + 16 + h * 4) * N);
            }
        }
        #pragma unroll
        for (int ks = 0; ks < 16; ks += 8) {
            unsigned a[4][4];
            #pragma unroll
            for (int mi = 0; mi < 4; mi++) {
                int mr0 = wm + mi * 16 + r, mr1 = mr0 + 8;
                int c0 = ks + quad, c1 = c0 + 4;
                a[mi][0] = Asm[buf][a_off(mr0, c0)];
                a[mi][1] = Asm[buf][a_off(mr1, c0)];
                a[mi][2] = Asm[buf][a_off(mr0, c1)];
                a[mi][3] = Asm[buf][a_off(mr1, c1)];
            }
            unsigned b[8][2];
            #pragma unroll
            for (int ni = 0; ni < 8; ni++) {
                int ncol = wn + ni * 8 + r;
                b[ni][0] = Bsm[buf][ks + quad][ncol];
                b[ni][1] = Bsm[buf][ks + quad + 4][ncol];
            }
            #pragma unroll
            for (int mi = 0; mi < 4; mi++)
                #pragma unroll
                for (int ni = 0; ni < 8; ni++) {
                    asm volatile(
                        "mma.sync.aligned.m16n8k8.row.col.f32.tf32.tf32.f32 "
                        "{%0,%1,%2,%3}, {%4,%5,%6,%7}, {%8,%9}, {%0,%1,%2,%3};"
                        : "+f"(acc[mi][ni][0]), "+f"(acc[mi][ni][1]),
                          "+f"(acc[mi][ni][2]), "+f"(acc[mi][ni][3])
                        : "r"(a[mi][0]), "r"(a[mi][1]), "r"(a[mi][2]), "r"(a[mi][3]),
                          "r"(b[ni][0]), "r"(b[ni][1]));
                }
        }
        if (more) {
            #pragma unroll
            for (int h = 0; h < 4; h++) {
                float4 v = ra[h];
                if (TRANSA) {
                    int kg = kt + 16 + ak;
                    v.x = fmaxf(0.f, v.x * scale[kg + 0] + shift[kg + 0]);
                    v.y = fmaxf(0.f, v.y * scale[kg + 1] + shift[kg + 1]);
                    v.z = fmaxf(0.f, v.z * scale[kg + 2] + shift[kg + 2]);
                    v.w = fmaxf(0.f, v.w * scale[kg + 3] + shift[kg + 3]);
                }
                uint4 u;
                CVT_TF32(u.x, v.x); CVT_TF32(u.y, v.y); CVT_TF32(u.z, v.z); CVT_TF32(u.w, v.w);
                int m = am + h * 32;
                int ck = (((ak >> 2) ^ (m >> 1)) & 3) << 2;
                *(uint4*)&Asm[buf ^ 1][m * 16 + ck] = u;
                float4 w4 = rb[h];
                uint4 ub;
                CVT_TF32(ub.x, w4.x); CVT_TF32(ub.y, w4.y); CVT_TF32(ub.z, w4.z); CVT_TF32(ub.w, w4.w);
                *(uint4*)&Bsm[buf ^ 1][bk + h * 4][bn] = ub;
            }
        }
        __syncthreads();
        buf ^= 1;
    }

    // ---- epilogue ----
    #pragma unroll
    for (int mi = 0; mi < 4; mi++) {
        #pragma unroll
        for (int ni = 0; ni < 8; ni++) {
            int row0 = m0 + wm + mi * 16 + r;
            int row1 = row0 + 8;
            int col  = n0 + wn + ni * 8 + 2 * quad;
            float2 v0 = make_float2(acc[mi][ni][0], acc[mi][ni][1]);
            float2 v1 = make_float2(acc[mi][ni][2], acc[mi][ni][3]);
            if (BIAS) {
                float b0v = bias[col], b1v = bias[col + 1];
                v0.x += b0v; v0.y += b1v;
                v1.x += b0v; v1.y += b1v;
            }
            if (COMBINE) {
                float2 e0 = *(const float2*)&E2[(long)row0 * FD + col];
                float2 e1 = *(const float2*)&E2[(long)row1 * FD + col];
                v0.x *= e0.x; v0.y *= e0.y;
                v1.x *= e1.x; v1.y *= e1.y;
                long br0 = (row0 < BB) ? row0 : (row0 - BB);
                long br1 = (row1 < BB) ? row1 : (row1 - BB);
                int  c0  = (row0 < BB) ? 0 : FD;
                int  c1  = (row1 < BB) ? 0 : FD;
                *(float2*)&C[br0 * (long)COMB + c0 + col] = v0;
                *(float2*)&C[br1 * (long)COMB + c1 + col] = v1;
            } else {
                *(float2*)&C[(long)row0 * N + col] = v0;
                *(float2*)&C[(long)row1 * N + col] = v1;
            }
        }
    }
}

// ---------------- BN stats -> scale/shift ----------------------------------
__global__ void bn_stats_kernel(const float* __restrict__ H, int N,
                                const float* __restrict__ g, const float* __restrict__ be,
                                float* __restrict__ scale, float* __restrict__ shift) {
    int lane = threadIdx.x & 31;
    int ty   = threadIdx.x >> 5;          // 0..15
    int col  = blockIdx.x * 32 + lane;
    float s = 0.f, sq = 0.f;
    for (int r = ty; r < BB; r += 16) {
        float v = H[(long)r * N + col];
        s += v; sq += v * v;
    }
    __shared__ float ss[16][33], sqs[16][33];
    ss[ty][lane] = s; sqs[ty][lane] = sq;
    __syncthreads();
    if (ty == 0) {
        #pragma unroll
        for (int i = 1; i < 16; i++) { s += ss[i][lane]; sq += sqs[i][lane]; }
        float mean = s * (1.f / BB);
        float var  = sq * (1.f / BB) - mean * mean;
        float sc   = g[col] * rsqrtf(var + EPSV);
        scale[col] = sc;
        shift[col] = be[col] - mean * sc;
    }
}

// ---------------- final: BN+ReLU dot w2 + linear + sigmoid -----------------
__global__ void final_kernel(const float* __restrict__ H1,
                             const float* __restrict__ scale, const float* __restrict__ shift,
                             const float* __restrict__ w2, const float* __restrict__ b2,
                             const float* __restrict__ lin, const float* __restrict__ bias0,
                             float* __restrict__ out) {
    int warp = threadIdx.x >> 5, lane = threadIdx.x & 31;
    int row = blockIdx.x * 8 + warp;
    float acc = 0.f;
    #pragma unroll 4
    for (int k = lane; k < H1N; k += 32) {
        float v = H1[(long)row * H1N + k];
        v = fmaxf(0.f, v * scale[k] + shift[k]);
        acc += v * w2[k];
    }
    #pragma unroll
    for (int o = 16; o > 0; o >>= 1) acc += __shfl_xor_sync(0xffffffffu, acc, o);
    if (lane == 0) {
        float logit = acc + b2[0] + lin[row] + bias0[0];
        out[row] = 1.f / (1.f + expf(-logit));
    }
}

// ---------------------------------------------------------------------------
extern "C" void kernel_launch(void* const* d_in, const int* in_sizes, int n_in,
                              void* d_out, int out_size) {
    const int*   x    = (const int*)d_in[0];
    const float* emb  = (const float*)d_in[1];
    const float* lint = (const float*)d_in[2];
    const float* bias = (const float*)d_in[3];
    const float* sw1  = (const float*)d_in[4];
    const float* sw2  = (const float*)d_in[5];
    const float* bilW = (const float*)d_in[6];
    const float* w0   = (const float*)d_in[7];
    const float* b0   = (const float*)d_in[8];
    const float* g0   = (const float*)d_in[9];
    const float* be0  = (const float*)d_in[10];
    const float* w1   = (const float*)d_in[11];
    const float* b1   = (const float*)d_in[12];
    const float* g1   = (const float*)d_in[13];
    const float* be1  = (const float*)d_in[14];
    const float* w2   = (const float*)d_in[15];
    const float* b2   = (const float*)d_in[16];
    float* out = (float*)d_out;

    float *E2, *WT, *comb, *h0, *h1, *lin, *sc0, *sh0, *sc1, *sh1;
    cudaGetSymbolAddress((void**)&E2,   g_E2);
    cudaGetSymbolAddress((void**)&WT,   g_WT);
    cudaGetSymbolAddress((void**)&comb, g_comb);
    cudaGetSymbolAddress((void**)&h0,   g_h0);
    cudaGetSymbolAddress((void**)&h1,   g_h1);
    cudaGetSymbolAddress((void**)&lin,  g_lin);
    cudaGetSymbolAddress((void**)&sc0,  g_scale0);
    cudaGetSymbolAddress((void**)&sh0,  g_shift0);
    cudaGetSymbolAddress((void**)&sc1,  g_scale1);
    cudaGetSymbolAddress((void**)&sh1,  g_shift1);

    transposeW_kernel<<<(FD * FD) / 256, 256>>>(bilW, WT);
    gather_se_kernel<<<BB, 256>>>(x, emb, lint, sw1, sw2, E2, lin);
    // G1: comb = (E2 @ WT) * E2 scattered into [p|q] layout
    tf32gemm_kernel<false, false, true><<<dim3(2 * BB / 128, FD / 128), 128>>>(
        E2, WT, comb, 2 * BB, FD, FD, nullptr, nullptr, nullptr, E2);
    // G2: h0 = comb @ w0 + b0
    tf32gemm_kernel<false, true, false><<<dim3(BB / 128, H0N / 128), 128>>>(
        comb, w0, h0, BB, H0N, COMB, b0, nullptr, nullptr, nullptr);
    bn_stats_kernel<<<H0N / 32, 512>>>(h0, H0N, g0, be0, sc0, sh0);
    // G3: h1 = relu(BN(h0)) @ w1 + b1
    tf32gemm_kernel<true, true, false><<<dim3(BB / 128, H1N / 128), 128>>>(
        h0, w1, h1, BB, H1N, H0N, b1, sc0, sh0, nullptr);
    bn_stats_kernel<<<H1N / 32, 512>>>(h1, H1N, g1, be1, sc1, sh1);
    final_kernel<<<BB / 8, 256>>>(h1, sc1, sh1, w2, b2, lin, bias, out);
}